// round 14
// baseline (speedup 1.0000x reference)
#include <cuda_runtime.h>
#include <math.h>

#define B_    16
#define T_    64
#define N_    256
#define D_    64
#define TWOD_ 128
#define ND_   16384   // N_*D_ : element stride between consecutive t rows

// Pre-transposed weights: W12t,W13t,W14t as [128][64]; W15t,W16t as [64][64]
__device__ __align__(16) float g_Wt[3 * TWOD_ * D_ + 2 * D_ * D_];   // 32768 floats

__global__ void transpose_weights(const float* __restrict__ W12,
                                  const float* __restrict__ W13,
                                  const float* __restrict__ W14,
                                  const float* __restrict__ W15,
                                  const float* __restrict__ W16)
{
    int idx = blockIdx.x * blockDim.x + threadIdx.x;
    if (idx < 8192) {
        int j = idx >> 7, c = idx & 127;
        g_Wt[c * 64 + j] = W12[idx];
    } else if (idx < 16384) {
        int k = idx - 8192; int j = k >> 7, c = k & 127;
        g_Wt[8192 + c * 64 + j] = W13[k];
    } else if (idx < 24576) {
        int k = idx - 16384; int j = k >> 7, c = k & 127;
        g_Wt[16384 + c * 64 + j] = W14[k];
    } else if (idx < 28672) {
        int k = idx - 24576; int j = k >> 6, c = k & 63;
        g_Wt[24576 + c * 64 + j] = W15[k];
    } else if (idx < 32768) {
        int k = idx - 28672; int j = k >> 6, c = k & 63;
        g_Wt[28672 + c * 64 + j] = W16[k];
    }
}

// ---------------- packed fp32x2 helpers (sm_103a FFMA2 path, PTX-only) ----------------
__device__ __forceinline__ unsigned long long pk2(float v) {
    unsigned long long r;
    asm("mov.b64 %0, {%1, %2};" : "=l"(r) : "f"(v), "f"(v));
    return r;
}
__device__ __forceinline__ void upk2(unsigned long long v, float& lo, float& hi) {
    asm("mov.b64 {%0, %1}, %2;" : "=f"(lo), "=f"(hi) : "l"(v));
}
__device__ __forceinline__ unsigned long long fma2(unsigned long long a,
                                                   unsigned long long b,
                                                   unsigned long long c) {
    unsigned long long d;
    asm("fma.rn.f32x2 %0, %1, %2, %3;" : "=l"(d) : "l"(a), "l"(b), "l"(c));
    return d;
}
__device__ __forceinline__ unsigned long long mul2(unsigned long long a,
                                                   unsigned long long b) {
    unsigned long long d;
    asm("mul.rn.f32x2 %0, %1, %2;" : "=l"(d) : "l"(a), "l"(b));
    return d;
}
__device__ __forceinline__ float psum2(unsigned long long v) {
    float lo, hi; upk2(v, lo, hi); return lo + hi;
}

__device__ __forceinline__ float gelu_f(float x) {
    // exact erf GELU (matches jax.nn.gelu(approximate=False))
    return 0.5f * x * (1.0f + erff(x * 0.7071067811865475f));
}

// SMEM layout (floats):
//   sH  @ 0     : 8704  (H 64x132=8448; reused: sO 64x68 @[0..4352), W16 buf @[4352..8448))
//   sWc @ 8704  : 6144  (QKV chunk: wQ/wK/wV 32x64 each; later W15t full in [0..4096))
//   sQ  @ 14848 : 4096  (later sM 64x68=4352, spilling into dead sK start)
//   sK  @ 18944 : 4096
//   sV  @ 23040 : 4096
// total 27136 floats = 108544 B -> 2 CTAs/SM
#define SMEM_FLOATS 27136

__global__ __launch_bounds__(256, 2)
void tam_kernel(const float* __restrict__ X,  const float* __restrict__ STE,
                const float* __restrict__ b12, const float* __restrict__ b13,
                const float* __restrict__ b14, const float* __restrict__ b15,
                const float* __restrict__ b16, float* __restrict__ out)
{
    extern __shared__ float sm[];
    float* sH  = sm;
    float* sWc = sm + 8704;
    float* sQ  = sm + 14848;
    float* sK  = sm + 18944;
    float* sV  = sm + 23040;

    const int n = blockIdx.x, b = blockIdx.y;
    const int tid = threadIdx.x;
    const int baseX = (b * T_ * N_ + n) * D_;

    // ---------------- load H = [X | STE] : 64 rows x 128, stride 132 ----------------
    for (int i = tid; i < T_ * TWOD_; i += 256) {
        int t = i >> 7, c = i & 127;
        int g = baseX + t * ND_ + (c & 63);
        sH[t * 132 + c] = (c < 64) ? X[g] : STE[g];
    }
    __syncthreads();

    // ================= fused QKV: tile 8t x 2j per thread =================
    // jq = j-pair base (one ulonglong of W per matrix per c), tq8 = 8-row block.
    // Per c-step: 8 H floats + 6 W floats feed 48 FMAs (24 FFMA2).
    const int jq  = (tid & 31) * 2;
    const int tq8 = (tid >> 5) * 8;

    unsigned long long aQ[8], aK[8], aV[8];
    #pragma unroll
    for (int r = 0; r < 8; r++) { aQ[r] = 0ull; aK[r] = 0ull; aV[r] = 0ull; }

    for (int ch = 0; ch < 4; ch++) {               // 4 chunks of 32 c-rows
        // cooperative load of 32x64 chunk of each of W12t/W13t/W14t (6144 floats)
        #pragma unroll
        for (int i = 0; i < 6; i++) {
            int k = i * 256 + tid;                 // float4 index 0..1535
            int m = k >> 9, off = (k & 511) << 2;
            *(float4*)&sWc[m * 2048 + off] =
                *(const float4*)&g_Wt[m * 8192 + ch * 2048 + off];
        }
        __syncthreads();

        #pragma unroll 2
        for (int c2 = 0; c2 < 16; c2++) {
            const int cc = (ch << 5) + (c2 << 1);
            float2 h[8];
            #pragma unroll
            for (int r = 0; r < 8; r++)
                h[r] = *(const float2*)&sH[(tq8 + r) * 132 + cc];

            #pragma unroll
            for (int i = 0; i < 2; i++) {
                const int c = (c2 << 1) + i;
                unsigned long long wq = *(const unsigned long long*)&sWc[c * 64 + jq];
                unsigned long long wk = *(const unsigned long long*)&sWc[2048 + c * 64 + jq];
                unsigned long long wv = *(const unsigned long long*)&sWc[4096 + c * 64 + jq];
                #pragma unroll
                for (int r = 0; r < 8; r++) {
                    unsigned long long Hc = pk2(i ? h[r].y : h[r].x);
                    aQ[r] = fma2(Hc, wq, aQ[r]);
                    aK[r] = fma2(Hc, wk, aK[r]);
                    aV[r] = fma2(Hc, wv, aV[r]);
                }
            }
        }
        __syncthreads();
    }

    // QKV epilogue: bias + exact gelu, store j-pair per row
    {
        const float2 bq = make_float2(b12[jq], b12[jq + 1]);
        const float2 bk = make_float2(b13[jq], b13[jq + 1]);
        const float2 bv = make_float2(b14[jq], b14[jq + 1]);
        #pragma unroll
        for (int r = 0; r < 8; r++) {
            float f0, f1;
            upk2(aQ[r], f0, f1);
            *(float2*)&sQ[(tq8 + r) * 64 + jq] =
                make_float2(gelu_f(f0 + bq.x), gelu_f(f1 + bq.y));
            upk2(aK[r], f0, f1);
            *(float2*)&sK[(tq8 + r) * 64 + jq] =
                make_float2(gelu_f(f0 + bk.x), gelu_f(f1 + bk.y));
            upk2(aV[r], f0, f1);
            *(float2*)&sV[(tq8 + r) * 64 + jq] =
                make_float2(gelu_f(f0 + bv.x), gelu_f(f1 + bv.y));
        }
    }
    __syncthreads();

    // ---------------- overlap: load W15 -> sWc[0..4096), W16 -> sH[4352..8448) ----------------
    #pragma unroll
    for (int i = 0; i < 4; i++) {
        int k = (i * 256 + tid) << 2;              // float offset 0..4092
        *(float4*)&sWc[k]        = *(const float4*)&g_Wt[24576 + k];
        *(float4*)&sH[4352 + k]  = *(const float4*)&g_Wt[28672 + k];
    }

    // ---------------- causal attention: two queries per thread, shared K/V loads ----------------
    // Logits are small enough (gelu-bounded q,k, d=8) that exp cannot overflow fp32;
    // softmax shift-invariance makes skipping the max pass exact up to rounding.
    {
        const int h8 = (tid & 7) * 8;
        const int tA = tid >> 3;                   // query A: tA, query B: tA + 32
        const float scale = 0.35355339059327376f;  // 1/sqrt(8)
        float* sO = sH;                            // output tile, stride 68, in [0..4352)

        const ulonglong2 q1a = *(const ulonglong2*)&sQ[tA * 64 + h8];
        const ulonglong2 q1b = *(const ulonglong2*)&sQ[tA * 64 + h8 + 4];
        const ulonglong2 q2a = *(const ulonglong2*)&sQ[(tA + 32) * 64 + h8];
        const ulonglong2 q2b = *(const ulonglong2*)&sQ[(tA + 32) * 64 + h8 + 4];

        unsigned long long ac1[4] = {0,0,0,0}, ac2[4] = {0,0,0,0};
        float s1 = 0.f, s2 = 0.f;

        // common range: s in [0, tA] — K/V loaded once, both queries updated
        #pragma unroll 2
        for (int s = 0; s <= tA; s++) {
            const ulonglong2 ka = *(const ulonglong2*)&sK[s * 64 + h8];
            const ulonglong2 kb = *(const ulonglong2*)&sK[s * 64 + h8 + 4];
            unsigned long long d1 = mul2(q1a.x, ka.x);
            d1 = fma2(q1a.y, ka.y, d1); d1 = fma2(q1b.x, kb.x, d1); d1 = fma2(q1b.y, kb.y, d1);
            unsigned long long d2 = mul2(q2a.x, ka.x);
            d2 = fma2(q2a.y, ka.y, d2); d2 = fma2(q2b.x, kb.x, d2); d2 = fma2(q2b.y, kb.y, d2);
            float e1 = __expf(psum2(d1) * scale);
            float e2 = __expf(psum2(d2) * scale);
            s1 += e1; s2 += e2;
            const ulonglong2 va = *(const ulonglong2*)&sV[s * 64 + h8];
            const ulonglong2 vb = *(const ulonglong2*)&sV[s * 64 + h8 + 4];
            unsigned long long E1 = pk2(e1), E2 = pk2(e2);
            ac1[0] = fma2(E1, va.x, ac1[0]); ac1[1] = fma2(E1, va.y, ac1[1]);
            ac1[2] = fma2(E1, vb.x, ac1[2]); ac1[3] = fma2(E1, vb.y, ac1[3]);
            ac2[0] = fma2(E2, va.x, ac2[0]); ac2[1] = fma2(E2, va.y, ac2[1]);
            ac2[2] = fma2(E2, vb.x, ac2[2]); ac2[3] = fma2(E2, vb.y, ac2[3]);
        }
        // tail range: s in (tA, tA+32] — query B only; fixed 32 trips, no divergence
        #pragma unroll 4
        for (int k2 = 1; k2 <= 32; k2++) {
            const int s = tA + k2;
            const ulonglong2 ka = *(const ulonglong2*)&sK[s * 64 + h8];
            const ulonglong2 kb = *(const ulonglong2*)&sK[s * 64 + h8 + 4];
            unsigned long long d2 = mul2(q2a.x, ka.x);
            d2 = fma2(q2a.y, ka.y, d2); d2 = fma2(q2b.x, kb.x, d2); d2 = fma2(q2b.y, kb.y, d2);
            float e2 = __expf(psum2(d2) * scale);
            s2 += e2;
            const ulonglong2 va = *(const ulonglong2*)&sV[s * 64 + h8];
            const ulonglong2 vb = *(const ulonglong2*)&sV[s * 64 + h8 + 4];
            unsigned long long E2 = pk2(e2);
            ac2[0] = fma2(E2, va.x, ac2[0]); ac2[1] = fma2(E2, va.y, ac2[1]);
            ac2[2] = fma2(E2, vb.x, ac2[2]); ac2[3] = fma2(E2, vb.y, ac2[3]);
        }

        float inv1 = 1.0f / s1, inv2 = 1.0f / s2;
        float f0, f1;
        float4 o;
        upk2(ac1[0], f0, f1); o.x = f0 * inv1; o.y = f1 * inv1;
        upk2(ac1[1], f0, f1); o.z = f0 * inv1; o.w = f1 * inv1;
        *(float4*)&sO[tA * 68 + h8] = o;
        upk2(ac1[2], f0, f1); o.x = f0 * inv1; o.y = f1 * inv1;
        upk2(ac1[3], f0, f1); o.z = f0 * inv1; o.w = f1 * inv1;
        *(float4*)&sO[tA * 68 + h8 + 4] = o;
        upk2(ac2[0], f0, f1); o.x = f0 * inv2; o.y = f1 * inv2;
        upk2(ac2[1], f0, f1); o.z = f0 * inv2; o.w = f1 * inv2;
        *(float4*)&sO[(tA + 32) * 68 + h8] = o;
        upk2(ac2[2], f0, f1); o.x = f0 * inv2; o.y = f1 * inv2;
        upk2(ac2[3], f0, f1); o.z = f0 * inv2; o.w = f1 * inv2;
        *(float4*)&sO[(tA + 32) * 68 + h8 + 4] = o;
    }
    __syncthreads();

    // ================= MLP stages: tile 4t x 4j per thread =================
    const int jm = (tid & 15) * 4;
    const int tm = (tid >> 4) * 4;
    float* sM = sQ;                                // stride 68 (spills into dead sK)

    // ---------------- MLP stage 1: sM = gelu(sO @ W15^T + b15) ----------------
    {
        const float* sO = sH;
        unsigned long long a[4][2];
        #pragma unroll
        for (int r = 0; r < 4; r++) { a[r][0] = 0ull; a[r][1] = 0ull; }

        #pragma unroll 2
        for (int c4 = 0; c4 < 16; c4++) {
            const int cc = c4 << 2;
            float ha[4][4];
            #pragma unroll
            for (int r = 0; r < 4; r++) {
                float4 hv = *(const float4*)&sO[(tm + r) * 68 + cc];
                ha[r][0] = hv.x; ha[r][1] = hv.y; ha[r][2] = hv.z; ha[r][3] = hv.w;
            }
            #pragma unroll
            for (int i = 0; i < 4; i++) {
                const ulonglong2 w = *(const ulonglong2*)&sWc[(cc + i) * 64 + jm];
                #pragma unroll
                for (int r = 0; r < 4; r++) {
                    unsigned long long Hc = pk2(ha[r][i]);
                    a[r][0] = fma2(Hc, w.x, a[r][0]);
                    a[r][1] = fma2(Hc, w.y, a[r][1]);
                }
            }
        }
        const float4 bb = *(const float4*)&b15[jm];
        #pragma unroll
        for (int r = 0; r < 4; r++) {
            float f0, f1, f2, f3;
            upk2(a[r][0], f0, f1);
            upk2(a[r][1], f2, f3);
            float4 o;
            o.x = gelu_f(f0 + bb.x); o.y = gelu_f(f1 + bb.y);
            o.z = gelu_f(f2 + bb.z); o.w = gelu_f(f3 + bb.w);
            *(float4*)&sM[(tm + r) * 68 + jm] = o;
        }
    }
    __syncthreads();

    // ---------------- MLP stage 2: out = sM @ W16^T + b16 -> GMEM ----------------
    {
        const float* w16 = sH + 4352;              // W16t [64][64]
        unsigned long long a[4][2];
        #pragma unroll
        for (int r = 0; r < 4; r++) { a[r][0] = 0ull; a[r][1] = 0ull; }

        #pragma unroll 2
        for (int c4 = 0; c4 < 16; c4++) {
            const int cc = c4 << 2;
            float ha[4][4];
            #pragma unroll
            for (int r = 0; r < 4; r++) {
                float4 hv = *(const float4*)&sM[(tm + r) * 68 + cc];
                ha[r][0] = hv.x; ha[r][1] = hv.y; ha[r][2] = hv.z; ha[r][3] = hv.w;
            }
            #pragma unroll
            for (int i = 0; i < 4; i++) {
                const ulonglong2 w = *(const ulonglong2*)&w16[(cc + i) * 64 + jm];
                #pragma unroll
                for (int r = 0; r < 4; r++) {
                    unsigned long long Hc = pk2(ha[r][i]);
                    a[r][0] = fma2(Hc, w.x, a[r][0]);
                    a[r][1] = fma2(Hc, w.y, a[r][1]);
                }
            }
        }
        const float4 bb = *(const float4*)&b16[jm];
        #pragma unroll
        for (int r = 0; r < 4; r++) {
            float f0, f1, f2, f3;
            upk2(a[r][0], f0, f1);
            upk2(a[r][1], f2, f3);
            float4 o;
            o.x = f0 + bb.x; o.y = f1 + bb.y; o.z = f2 + bb.z; o.w = f3 + bb.w;
            *(float4*)&out[baseX + (tm + r) * ND_ + jm] = o;
        }
    }
}

extern "C" void kernel_launch(void* const* d_in, const int* in_sizes, int n_in,
                              void* d_out, int out_size)
{
    const float* X   = (const float*)d_in[0];
    const float* STE = (const float*)d_in[1];
    const float* W12 = (const float*)d_in[2];
    const float* b12 = (const float*)d_in[3];
    const float* W13 = (const float*)d_in[4];
    const float* b13 = (const float*)d_in[5];
    const float* W14 = (const float*)d_in[6];
    const float* b14 = (const float*)d_in[7];
    const float* W15 = (const float*)d_in[8];
    const float* b15 = (const float*)d_in[9];
    const float* W16 = (const float*)d_in[10];
    const float* b16 = (const float*)d_in[11];
    float* out = (float*)d_out;

    cudaFuncSetAttribute(tam_kernel,
                         cudaFuncAttributeMaxDynamicSharedMemorySize,
                         SMEM_FLOATS * (int)sizeof(float));

    transpose_weights<<<128, 256>>>(W12, W13, W14, W15, W16);

    dim3 grid(N_, B_);
    tam_kernel<<<grid, 256, SMEM_FLOATS * sizeof(float)>>>(
        X, STE, b12, b13, b14, b15, b16, out);
}

// round 15
// speedup vs baseline: 1.0002x; 1.0002x over previous
#include <cuda_runtime.h>
#include <math.h>

#define B_    16
#define T_    64
#define N_    256
#define D_    64
#define TWOD_ 128
#define ND_   16384   // N_*D_ : element stride between consecutive t rows

// Pre-transposed weights: W12t,W13t,W14t as [128][64]; W15t,W16t as [64][64]
__device__ __align__(16) float g_Wt[3 * TWOD_ * D_ + 2 * D_ * D_];   // 32768 floats

__global__ void transpose_weights(const float* __restrict__ W12,
                                  const float* __restrict__ W13,
                                  const float* __restrict__ W14,
                                  const float* __restrict__ W15,
                                  const float* __restrict__ W16)
{
    int idx = blockIdx.x * blockDim.x + threadIdx.x;
    if (idx < 8192) {
        int j = idx >> 7, c = idx & 127;
        g_Wt[c * 64 + j] = W12[idx];
    } else if (idx < 16384) {
        int k = idx - 8192; int j = k >> 7, c = k & 127;
        g_Wt[8192 + c * 64 + j] = W13[k];
    } else if (idx < 24576) {
        int k = idx - 16384; int j = k >> 7, c = k & 127;
        g_Wt[16384 + c * 64 + j] = W14[k];
    } else if (idx < 28672) {
        int k = idx - 24576; int j = k >> 6, c = k & 63;
        g_Wt[24576 + c * 64 + j] = W15[k];
    } else if (idx < 32768) {
        int k = idx - 28672; int j = k >> 6, c = k & 63;
        g_Wt[28672 + c * 64 + j] = W16[k];
    }
}

// ---------------- packed fp32x2 helpers (sm_103a FFMA2 path, PTX-only) ----------------
__device__ __forceinline__ unsigned long long pk2(float v) {
    unsigned long long r;
    asm("mov.b64 %0, {%1, %2};" : "=l"(r) : "f"(v), "f"(v));
    return r;
}
__device__ __forceinline__ void upk2(unsigned long long v, float& lo, float& hi) {
    asm("mov.b64 {%0, %1}, %2;" : "=f"(lo), "=f"(hi) : "l"(v));
}
__device__ __forceinline__ unsigned long long fma2(unsigned long long a,
                                                   unsigned long long b,
                                                   unsigned long long c) {
    unsigned long long d;
    asm("fma.rn.f32x2 %0, %1, %2, %3;" : "=l"(d) : "l"(a), "l"(b), "l"(c));
    return d;
}
__device__ __forceinline__ unsigned long long mul2(unsigned long long a,
                                                   unsigned long long b) {
    unsigned long long d;
    asm("mul.rn.f32x2 %0, %1, %2;" : "=l"(d) : "l"(a), "l"(b));
    return d;
}
__device__ __forceinline__ float psum2(unsigned long long v) {
    float lo, hi; upk2(v, lo, hi); return lo + hi;
}

__device__ __forceinline__ float gelu_f(float x) {
    // exact erf GELU (matches jax.nn.gelu(approximate=False))
    return 0.5f * x * (1.0f + erff(x * 0.7071067811865475f));
}

// SMEM layout (floats):
//   sH  @ 0     : 8704  (H 64x132=8448; reused: sO 64x68 @[0..4352), W16 buf @[4352..8448))
//   sWc @ 8704  : 6144  (QKV chunk: wQ/wK/wV 32x64 each; later W15t full in [0..4096))
//   sQ  @ 14848 : 4096  (later sM 64x68=4352, spilling into dead sK start)
//   sK  @ 18944 : 4096
//   sV  @ 23040 : 4096
// total 27136 floats = 108544 B -> 2 CTAs/SM
#define SMEM_FLOATS 27136

__global__ __launch_bounds__(256, 2)
void tam_kernel(const float* __restrict__ X,  const float* __restrict__ STE,
                const float* __restrict__ b12, const float* __restrict__ b13,
                const float* __restrict__ b14, const float* __restrict__ b15,
                const float* __restrict__ b16, float* __restrict__ out)
{
    extern __shared__ float sm[];
    float* sH  = sm;
    float* sWc = sm + 8704;
    float* sQ  = sm + 14848;
    float* sK  = sm + 18944;
    float* sV  = sm + 23040;

    const int n = blockIdx.x, b = blockIdx.y;
    const int tid = threadIdx.x;
    const int baseX = (b * T_ * N_ + n) * D_;

    // ---------------- load H = [X | STE] : 64 rows x 128, stride 132 ----------------
    for (int i = tid; i < T_ * TWOD_; i += 256) {
        int t = i >> 7, c = i & 127;
        int g = baseX + t * ND_ + (c & 63);
        sH[t * 132 + c] = (c < 64) ? X[g] : STE[g];
    }
    __syncthreads();

    // ================= fused QKV: tile 8t x 2j per thread =================
    // jq = j-pair base (one ulonglong of W per matrix per c), tq8 = 8-row block.
    // Per c-step: 8 H floats + 6 W floats feed 48 FMAs (24 FFMA2).
    const int jq  = (tid & 31) * 2;
    const int tq8 = (tid >> 5) * 8;

    unsigned long long aQ[8], aK[8], aV[8];
    #pragma unroll
    for (int r = 0; r < 8; r++) { aQ[r] = 0ull; aK[r] = 0ull; aV[r] = 0ull; }

    for (int ch = 0; ch < 4; ch++) {               // 4 chunks of 32 c-rows
        // cooperative load of 32x64 chunk of each of W12t/W13t/W14t (6144 floats)
        #pragma unroll
        for (int i = 0; i < 6; i++) {
            int k = i * 256 + tid;                 // float4 index 0..1535
            int m = k >> 9, off = (k & 511) << 2;
            *(float4*)&sWc[m * 2048 + off] =
                *(const float4*)&g_Wt[m * 8192 + ch * 2048 + off];
        }
        __syncthreads();

        #pragma unroll 2
        for (int c2 = 0; c2 < 16; c2++) {
            const int cc = (ch << 5) + (c2 << 1);
            float2 h[8];
            #pragma unroll
            for (int r = 0; r < 8; r++)
                h[r] = *(const float2*)&sH[(tq8 + r) * 132 + cc];

            #pragma unroll
            for (int i = 0; i < 2; i++) {
                const int c = (c2 << 1) + i;
                unsigned long long wq = *(const unsigned long long*)&sWc[c * 64 + jq];
                unsigned long long wk = *(const unsigned long long*)&sWc[2048 + c * 64 + jq];
                unsigned long long wv = *(const unsigned long long*)&sWc[4096 + c * 64 + jq];
                #pragma unroll
                for (int r = 0; r < 8; r++) {
                    unsigned long long Hc = pk2(i ? h[r].y : h[r].x);
                    aQ[r] = fma2(Hc, wq, aQ[r]);
                    aK[r] = fma2(Hc, wk, aK[r]);
                    aV[r] = fma2(Hc, wv, aV[r]);
                }
            }
        }
        __syncthreads();
    }

    // QKV epilogue: bias + exact gelu, store j-pair per row
    {
        const float2 bq = make_float2(b12[jq], b12[jq + 1]);
        const float2 bk = make_float2(b13[jq], b13[jq + 1]);
        const float2 bv = make_float2(b14[jq], b14[jq + 1]);
        #pragma unroll
        for (int r = 0; r < 8; r++) {
            float f0, f1;
            upk2(aQ[r], f0, f1);
            *(float2*)&sQ[(tq8 + r) * 64 + jq] =
                make_float2(gelu_f(f0 + bq.x), gelu_f(f1 + bq.y));
            upk2(aK[r], f0, f1);
            *(float2*)&sK[(tq8 + r) * 64 + jq] =
                make_float2(gelu_f(f0 + bk.x), gelu_f(f1 + bk.y));
            upk2(aV[r], f0, f1);
            *(float2*)&sV[(tq8 + r) * 64 + jq] =
                make_float2(gelu_f(f0 + bv.x), gelu_f(f1 + bv.y));
        }
    }
    __syncthreads();

    // ---------------- overlap: load W15 -> sWc[0..4096), W16 -> sH[4352..8448) ----------------
    #pragma unroll
    for (int i = 0; i < 4; i++) {
        int k = (i * 256 + tid) << 2;              // float offset 0..4092
        *(float4*)&sWc[k]        = *(const float4*)&g_Wt[24576 + k];
        *(float4*)&sH[4352 + k]  = *(const float4*)&g_Wt[28672 + k];
    }

    // ---------------- causal attention: two queries per thread, shared K/V loads ----------------
    // Logits are small enough (gelu-bounded q,k, d=8) that exp cannot overflow fp32;
    // softmax shift-invariance makes skipping the max pass exact up to rounding.
    {
        const int h8 = (tid & 7) * 8;
        const int tA = tid >> 3;                   // query A: tA, query B: tA + 32
        const float scale = 0.35355339059327376f;  // 1/sqrt(8)
        float* sO = sH;                            // output tile, stride 68, in [0..4352)

        const ulonglong2 q1a = *(const ulonglong2*)&sQ[tA * 64 + h8];
        const ulonglong2 q1b = *(const ulonglong2*)&sQ[tA * 64 + h8 + 4];
        const ulonglong2 q2a = *(const ulonglong2*)&sQ[(tA + 32) * 64 + h8];
        const ulonglong2 q2b = *(const ulonglong2*)&sQ[(tA + 32) * 64 + h8 + 4];

        unsigned long long ac1[4] = {0,0,0,0}, ac2[4] = {0,0,0,0};
        float s1 = 0.f, s2 = 0.f;

        // common range: s in [0, tA] — K/V loaded once, both queries updated
        #pragma unroll 2
        for (int s = 0; s <= tA; s++) {
            const ulonglong2 ka = *(const ulonglong2*)&sK[s * 64 + h8];
            const ulonglong2 kb = *(const ulonglong2*)&sK[s * 64 + h8 + 4];
            unsigned long long d1 = mul2(q1a.x, ka.x);
            d1 = fma2(q1a.y, ka.y, d1); d1 = fma2(q1b.x, kb.x, d1); d1 = fma2(q1b.y, kb.y, d1);
            unsigned long long d2 = mul2(q2a.x, ka.x);
            d2 = fma2(q2a.y, ka.y, d2); d2 = fma2(q2b.x, kb.x, d2); d2 = fma2(q2b.y, kb.y, d2);
            float e1 = __expf(psum2(d1) * scale);
            float e2 = __expf(psum2(d2) * scale);
            s1 += e1; s2 += e2;
            const ulonglong2 va = *(const ulonglong2*)&sV[s * 64 + h8];
            const ulonglong2 vb = *(const ulonglong2*)&sV[s * 64 + h8 + 4];
            unsigned long long E1 = pk2(e1), E2 = pk2(e2);
            ac1[0] = fma2(E1, va.x, ac1[0]); ac1[1] = fma2(E1, va.y, ac1[1]);
            ac1[2] = fma2(E1, vb.x, ac1[2]); ac1[3] = fma2(E1, vb.y, ac1[3]);
            ac2[0] = fma2(E2, va.x, ac2[0]); ac2[1] = fma2(E2, va.y, ac2[1]);
            ac2[2] = fma2(E2, vb.x, ac2[2]); ac2[3] = fma2(E2, vb.y, ac2[3]);
        }
        // tail range: s in (tA, tA+32] — query B only; fixed 32 trips, no divergence
        #pragma unroll 4
        for (int k2 = 1; k2 <= 32; k2++) {
            const int s = tA + k2;
            const ulonglong2 ka = *(const ulonglong2*)&sK[s * 64 + h8];
            const ulonglong2 kb = *(const ulonglong2*)&sK[s * 64 + h8 + 4];
            unsigned long long d2 = mul2(q2a.x, ka.x);
            d2 = fma2(q2a.y, ka.y, d2); d2 = fma2(q2b.x, kb.x, d2); d2 = fma2(q2b.y, kb.y, d2);
            float e2 = __expf(psum2(d2) * scale);
            s2 += e2;
            const ulonglong2 va = *(const ulonglong2*)&sV[s * 64 + h8];
            const ulonglong2 vb = *(const ulonglong2*)&sV[s * 64 + h8 + 4];
            unsigned long long E2 = pk2(e2);
            ac2[0] = fma2(E2, va.x, ac2[0]); ac2[1] = fma2(E2, va.y, ac2[1]);
            ac2[2] = fma2(E2, vb.x, ac2[2]); ac2[3] = fma2(E2, vb.y, ac2[3]);
        }

        float inv1 = 1.0f / s1, inv2 = 1.0f / s2;
        float f0, f1;
        float4 o;
        upk2(ac1[0], f0, f1); o.x = f0 * inv1; o.y = f1 * inv1;
        upk2(ac1[1], f0, f1); o.z = f0 * inv1; o.w = f1 * inv1;
        *(float4*)&sO[tA * 68 + h8] = o;
        upk2(ac1[2], f0, f1); o.x = f0 * inv1; o.y = f1 * inv1;
        upk2(ac1[3], f0, f1); o.z = f0 * inv1; o.w = f1 * inv1;
        *(float4*)&sO[tA * 68 + h8 + 4] = o;
        upk2(ac2[0], f0, f1); o.x = f0 * inv2; o.y = f1 * inv2;
        upk2(ac2[1], f0, f1); o.z = f0 * inv2; o.w = f1 * inv2;
        *(float4*)&sO[(tA + 32) * 68 + h8] = o;
        upk2(ac2[2], f0, f1); o.x = f0 * inv2; o.y = f1 * inv2;
        upk2(ac2[3], f0, f1); o.z = f0 * inv2; o.w = f1 * inv2;
        *(float4*)&sO[(tA + 32) * 68 + h8 + 4] = o;
    }
    __syncthreads();

    // ================= MLP stages: tile 4t x 4j per thread =================
    const int jm = (tid & 15) * 4;
    const int tm = (tid >> 4) * 4;
    float* sM = sQ;                                // stride 68 (spills into dead sK)

    // ---------------- MLP stage 1: sM = gelu(sO @ W15^T + b15) ----------------
    {
        const float* sO = sH;
        unsigned long long a[4][2];
        #pragma unroll
        for (int r = 0; r < 4; r++) { a[r][0] = 0ull; a[r][1] = 0ull; }

        #pragma unroll 2
        for (int c4 = 0; c4 < 16; c4++) {
            const int cc = c4 << 2;
            float ha[4][4];
            #pragma unroll
            for (int r = 0; r < 4; r++) {
                float4 hv = *(const float4*)&sO[(tm + r) * 68 + cc];
                ha[r][0] = hv.x; ha[r][1] = hv.y; ha[r][2] = hv.z; ha[r][3] = hv.w;
            }
            #pragma unroll
            for (int i = 0; i < 4; i++) {
                const ulonglong2 w = *(const ulonglong2*)&sWc[(cc + i) * 64 + jm];
                #pragma unroll
                for (int r = 0; r < 4; r++) {
                    unsigned long long Hc = pk2(ha[r][i]);
                    a[r][0] = fma2(Hc, w.x, a[r][0]);
                    a[r][1] = fma2(Hc, w.y, a[r][1]);
                }
            }
        }
        const float4 bb = *(const float4*)&b15[jm];
        #pragma unroll
        for (int r = 0; r < 4; r++) {
            float f0, f1, f2, f3;
            upk2(a[r][0], f0, f1);
            upk2(a[r][1], f2, f3);
            float4 o;
            o.x = gelu_f(f0 + bb.x); o.y = gelu_f(f1 + bb.y);
            o.z = gelu_f(f2 + bb.z); o.w = gelu_f(f3 + bb.w);
            *(float4*)&sM[(tm + r) * 68 + jm] = o;
        }
    }
    __syncthreads();

    // ---------------- MLP stage 2: out = sM @ W16^T + b16 -> GMEM ----------------
    {
        const float* w16 = sH + 4352;              // W16t [64][64]
        unsigned long long a[4][2];
        #pragma unroll
        for (int r = 0; r < 4; r++) { a[r][0] = 0ull; a[r][1] = 0ull; }

        #pragma unroll 2
        for (int c4 = 0; c4 < 16; c4++) {
            const int cc = c4 << 2;
            float ha[4][4];
            #pragma unroll
            for (int r = 0; r < 4; r++) {
                float4 hv = *(const float4*)&sM[(tm + r) * 68 + cc];
                ha[r][0] = hv.x; ha[r][1] = hv.y; ha[r][2] = hv.z; ha[r][3] = hv.w;
            }
            #pragma unroll
            for (int i = 0; i < 4; i++) {
                const ulonglong2 w = *(const ulonglong2*)&w16[(cc + i) * 64 + jm];
                #pragma unroll
                for (int r = 0; r < 4; r++) {
                    unsigned long long Hc = pk2(ha[r][i]);
                    a[r][0] = fma2(Hc, w.x, a[r][0]);
                    a[r][1] = fma2(Hc, w.y, a[r][1]);
                }
            }
        }
        const float4 bb = *(const float4*)&b16[jm];
        #pragma unroll
        for (int r = 0; r < 4; r++) {
            float f0, f1, f2, f3;
            upk2(a[r][0], f0, f1);
            upk2(a[r][1], f2, f3);
            float4 o;
            o.x = f0 + bb.x; o.y = f1 + bb.y; o.z = f2 + bb.z; o.w = f3 + bb.w;
            *(float4*)&out[baseX + (tm + r) * ND_ + jm] = o;
        }
    }
}

extern "C" void kernel_launch(void* const* d_in, const int* in_sizes, int n_in,
                              void* d_out, int out_size)
{
    const float* X   = (const float*)d_in[0];
    const float* STE = (const float*)d_in[1];
    const float* W12 = (const float*)d_in[2];
    const float* b12 = (const float*)d_in[3];
    const float* W13 = (const float*)d_in[4];
    const float* b13 = (const float*)d_in[5];
    const float* W14 = (const float*)d_in[6];
    const float* b14 = (const float*)d_in[7];
    const float* W15 = (const float*)d_in[8];
    const float* b15 = (const float*)d_in[9];
    const float* W16 = (const float*)d_in[10];
    const float* b16 = (const float*)d_in[11];
    float* out = (float*)d_out;

    cudaFuncSetAttribute(tam_kernel,
                         cudaFuncAttributeMaxDynamicSharedMemorySize,
                         SMEM_FLOATS * (int)sizeof(float));

    transpose_weights<<<128, 256>>>(W12, W13, W14, W15, W16);

    dim3 grid(N_, B_);
    tam_kernel<<<grid, 256, SMEM_FLOATS * sizeof(float)>>>(
        X, STE, b12, b13, b14, b15, b16, out);
}

// round 16
// speedup vs baseline: 1.0005x; 1.0003x over previous
#include <cuda_runtime.h>
#include <math.h>

#define B_    16
#define T_    64
#define N_    256
#define D_    64
#define TWOD_ 128
#define ND_   16384   // N_*D_ : element stride between consecutive t rows

// Pre-transposed weights: W12t,W13t,W14t as [128][64]; W15t,W16t as [64][64]
__device__ __align__(16) float g_Wt[3 * TWOD_ * D_ + 2 * D_ * D_];   // 32768 floats

__global__ void transpose_weights(const float* __restrict__ W12,
                                  const float* __restrict__ W13,
                                  const float* __restrict__ W14,
                                  const float* __restrict__ W15,
                                  const float* __restrict__ W16)
{
    int idx = blockIdx.x * blockDim.x + threadIdx.x;
    if (idx < 8192) {
        int j = idx >> 7, c = idx & 127;
        g_Wt[c * 64 + j] = W12[idx];
    } else if (idx < 16384) {
        int k = idx - 8192; int j = k >> 7, c = k & 127;
        g_Wt[8192 + c * 64 + j] = W13[k];
    } else if (idx < 24576) {
        int k = idx - 16384; int j = k >> 7, c = k & 127;
        g_Wt[16384 + c * 64 + j] = W14[k];
    } else if (idx < 28672) {
        int k = idx - 24576; int j = k >> 6, c = k & 63;
        g_Wt[24576 + c * 64 + j] = W15[k];
    } else if (idx < 32768) {
        int k = idx - 28672; int j = k >> 6, c = k & 63;
        g_Wt[28672 + c * 64 + j] = W16[k];
    }
}

// ---------------- packed fp32x2 helpers (sm_103a FFMA2 path, PTX-only) ----------------
__device__ __forceinline__ unsigned long long pk2(float v) {
    unsigned long long r;
    asm("mov.b64 %0, {%1, %2};" : "=l"(r) : "f"(v), "f"(v));
    return r;
}
__device__ __forceinline__ void upk2(unsigned long long v, float& lo, float& hi) {
    asm("mov.b64 {%0, %1}, %2;" : "=f"(lo), "=f"(hi) : "l"(v));
}
__device__ __forceinline__ unsigned long long fma2(unsigned long long a,
                                                   unsigned long long b,
                                                   unsigned long long c) {
    unsigned long long d;
    asm("fma.rn.f32x2 %0, %1, %2, %3;" : "=l"(d) : "l"(a), "l"(b), "l"(c));
    return d;
}
__device__ __forceinline__ unsigned long long mul2(unsigned long long a,
                                                   unsigned long long b) {
    unsigned long long d;
    asm("mul.rn.f32x2 %0, %1, %2;" : "=l"(d) : "l"(a), "l"(b));
    return d;
}
__device__ __forceinline__ float psum2(unsigned long long v) {
    float lo, hi; upk2(v, lo, hi); return lo + hi;
}

__device__ __forceinline__ float gelu_f(float x) {
    // exact erf GELU (matches jax.nn.gelu(approximate=False))
    return 0.5f * x * (1.0f + erff(x * 0.7071067811865475f));
}

// SMEM layout (floats):
//   sH  @ 0     : 8704  (H 64x132=8448; reused: sO 64x68 @[0..4352), W16 buf @[4352..8448))
//   sWc @ 8704  : 6144  (QKV chunk: wQ/wK/wV 32x64 each; later W15t full in [0..4096))
//   sQ  @ 14848 : 4096  (later sM 64x68=4352, spilling into dead sK start)
//   sK  @ 18944 : 4096
//   sV  @ 23040 : 4096
// total 27136 floats = 108544 B -> 2 CTAs/SM
#define SMEM_FLOATS 27136

__global__ __launch_bounds__(256, 2)
void tam_kernel(const float* __restrict__ X,  const float* __restrict__ STE,
                const float* __restrict__ b12, const float* __restrict__ b13,
                const float* __restrict__ b14, const float* __restrict__ b15,
                const float* __restrict__ b16, float* __restrict__ out)
{
    extern __shared__ float sm[];
    float* sH  = sm;
    float* sWc = sm + 8704;
    float* sQ  = sm + 14848;
    float* sK  = sm + 18944;
    float* sV  = sm + 23040;

    const int n = blockIdx.x, b = blockIdx.y;
    const int tid = threadIdx.x;
    const int baseX = (b * T_ * N_ + n) * D_;

    // ---------------- load H = [X | STE] : 64 rows x 128, stride 132 ----------------
    for (int i = tid; i < T_ * TWOD_; i += 256) {
        int t = i >> 7, c = i & 127;
        int g = baseX + t * ND_ + (c & 63);
        sH[t * 132 + c] = (c < 64) ? X[g] : STE[g];
    }
    __syncthreads();

    // ================= fused QKV: tile 8t x 2j per thread =================
    // jq = j-pair base (one ulonglong of W per matrix per c), tq8 = 8-row block.
    // Per c-step: 8 H floats + 6 W floats feed 48 FMAs (24 FFMA2).
    const int jq  = (tid & 31) * 2;
    const int tq8 = (tid >> 5) * 8;

    unsigned long long aQ[8], aK[8], aV[8];
    #pragma unroll
    for (int r = 0; r < 8; r++) { aQ[r] = 0ull; aK[r] = 0ull; aV[r] = 0ull; }

    for (int ch = 0; ch < 4; ch++) {               // 4 chunks of 32 c-rows
        // cooperative load of 32x64 chunk of each of W12t/W13t/W14t (6144 floats)
        #pragma unroll
        for (int i = 0; i < 6; i++) {
            int k = i * 256 + tid;                 // float4 index 0..1535
            int m = k >> 9, off = (k & 511) << 2;
            *(float4*)&sWc[m * 2048 + off] =
                *(const float4*)&g_Wt[m * 8192 + ch * 2048 + off];
        }
        __syncthreads();

        #pragma unroll 2
        for (int c2 = 0; c2 < 16; c2++) {
            const int cc = (ch << 5) + (c2 << 1);
            float2 h[8];
            #pragma unroll
            for (int r = 0; r < 8; r++)
                h[r] = *(const float2*)&sH[(tq8 + r) * 132 + cc];

            #pragma unroll
            for (int i = 0; i < 2; i++) {
                const int c = (c2 << 1) + i;
                unsigned long long wq = *(const unsigned long long*)&sWc[c * 64 + jq];
                unsigned long long wk = *(const unsigned long long*)&sWc[2048 + c * 64 + jq];
                unsigned long long wv = *(const unsigned long long*)&sWc[4096 + c * 64 + jq];
                #pragma unroll
                for (int r = 0; r < 8; r++) {
                    unsigned long long Hc = pk2(i ? h[r].y : h[r].x);
                    aQ[r] = fma2(Hc, wq, aQ[r]);
                    aK[r] = fma2(Hc, wk, aK[r]);
                    aV[r] = fma2(Hc, wv, aV[r]);
                }
            }
        }
        __syncthreads();
    }

    // QKV epilogue: bias + exact gelu, store j-pair per row
    {
        const float2 bq = make_float2(b12[jq], b12[jq + 1]);
        const float2 bk = make_float2(b13[jq], b13[jq + 1]);
        const float2 bv = make_float2(b14[jq], b14[jq + 1]);
        #pragma unroll
        for (int r = 0; r < 8; r++) {
            float f0, f1;
            upk2(aQ[r], f0, f1);
            *(float2*)&sQ[(tq8 + r) * 64 + jq] =
                make_float2(gelu_f(f0 + bq.x), gelu_f(f1 + bq.y));
            upk2(aK[r], f0, f1);
            *(float2*)&sK[(tq8 + r) * 64 + jq] =
                make_float2(gelu_f(f0 + bk.x), gelu_f(f1 + bk.y));
            upk2(aV[r], f0, f1);
            *(float2*)&sV[(tq8 + r) * 64 + jq] =
                make_float2(gelu_f(f0 + bv.x), gelu_f(f1 + bv.y));
        }
    }
    __syncthreads();

    // ---------------- overlap: load W15 -> sWc[0..4096), W16 -> sH[4352..8448) ----------------
    #pragma unroll
    for (int i = 0; i < 4; i++) {
        int k = (i * 256 + tid) << 2;              // float offset 0..4092
        *(float4*)&sWc[k]        = *(const float4*)&g_Wt[24576 + k];
        *(float4*)&sH[4352 + k]  = *(const float4*)&g_Wt[28672 + k];
    }

    // ---------------- causal attention: two queries per thread, shared K/V loads ----------------
    // Logits are small enough (gelu-bounded q,k, d=8) that exp cannot overflow fp32;
    // softmax shift-invariance makes skipping the max pass exact up to rounding.
    {
        const int h8 = (tid & 7) * 8;
        const int tA = tid >> 3;                   // query A: tA, query B: tA + 32
        const float scale = 0.35355339059327376f;  // 1/sqrt(8)
        float* sO = sH;                            // output tile, stride 68, in [0..4352)

        const ulonglong2 q1a = *(const ulonglong2*)&sQ[tA * 64 + h8];
        const ulonglong2 q1b = *(const ulonglong2*)&sQ[tA * 64 + h8 + 4];
        const ulonglong2 q2a = *(const ulonglong2*)&sQ[(tA + 32) * 64 + h8];
        const ulonglong2 q2b = *(const ulonglong2*)&sQ[(tA + 32) * 64 + h8 + 4];

        unsigned long long ac1[4] = {0,0,0,0}, ac2[4] = {0,0,0,0};
        float s1 = 0.f, s2 = 0.f;

        // common range: s in [0, tA] — K/V loaded once, both queries updated
        #pragma unroll 2
        for (int s = 0; s <= tA; s++) {
            const ulonglong2 ka = *(const ulonglong2*)&sK[s * 64 + h8];
            const ulonglong2 kb = *(const ulonglong2*)&sK[s * 64 + h8 + 4];
            unsigned long long d1 = mul2(q1a.x, ka.x);
            d1 = fma2(q1a.y, ka.y, d1); d1 = fma2(q1b.x, kb.x, d1); d1 = fma2(q1b.y, kb.y, d1);
            unsigned long long d2 = mul2(q2a.x, ka.x);
            d2 = fma2(q2a.y, ka.y, d2); d2 = fma2(q2b.x, kb.x, d2); d2 = fma2(q2b.y, kb.y, d2);
            float e1 = __expf(psum2(d1) * scale);
            float e2 = __expf(psum2(d2) * scale);
            s1 += e1; s2 += e2;
            const ulonglong2 va = *(const ulonglong2*)&sV[s * 64 + h8];
            const ulonglong2 vb = *(const ulonglong2*)&sV[s * 64 + h8 + 4];
            unsigned long long E1 = pk2(e1), E2 = pk2(e2);
            ac1[0] = fma2(E1, va.x, ac1[0]); ac1[1] = fma2(E1, va.y, ac1[1]);
            ac1[2] = fma2(E1, vb.x, ac1[2]); ac1[3] = fma2(E1, vb.y, ac1[3]);
            ac2[0] = fma2(E2, va.x, ac2[0]); ac2[1] = fma2(E2, va.y, ac2[1]);
            ac2[2] = fma2(E2, vb.x, ac2[2]); ac2[3] = fma2(E2, vb.y, ac2[3]);
        }
        // tail range: s in (tA, tA+32] — query B only; fixed 32 trips, no divergence
        #pragma unroll 4
        for (int k2 = 1; k2 <= 32; k2++) {
            const int s = tA + k2;
            const ulonglong2 ka = *(const ulonglong2*)&sK[s * 64 + h8];
            const ulonglong2 kb = *(const ulonglong2*)&sK[s * 64 + h8 + 4];
            unsigned long long d2 = mul2(q2a.x, ka.x);
            d2 = fma2(q2a.y, ka.y, d2); d2 = fma2(q2b.x, kb.x, d2); d2 = fma2(q2b.y, kb.y, d2);
            float e2 = __expf(psum2(d2) * scale);
            s2 += e2;
            const ulonglong2 va = *(const ulonglong2*)&sV[s * 64 + h8];
            const ulonglong2 vb = *(const ulonglong2*)&sV[s * 64 + h8 + 4];
            unsigned long long E2 = pk2(e2);
            ac2[0] = fma2(E2, va.x, ac2[0]); ac2[1] = fma2(E2, va.y, ac2[1]);
            ac2[2] = fma2(E2, vb.x, ac2[2]); ac2[3] = fma2(E2, vb.y, ac2[3]);
        }

        float inv1 = 1.0f / s1, inv2 = 1.0f / s2;
        float f0, f1;
        float4 o;
        upk2(ac1[0], f0, f1); o.x = f0 * inv1; o.y = f1 * inv1;
        upk2(ac1[1], f0, f1); o.z = f0 * inv1; o.w = f1 * inv1;
        *(float4*)&sO[tA * 68 + h8] = o;
        upk2(ac1[2], f0, f1); o.x = f0 * inv1; o.y = f1 * inv1;
        upk2(ac1[3], f0, f1); o.z = f0 * inv1; o.w = f1 * inv1;
        *(float4*)&sO[tA * 68 + h8 + 4] = o;
        upk2(ac2[0], f0, f1); o.x = f0 * inv2; o.y = f1 * inv2;
        upk2(ac2[1], f0, f1); o.z = f0 * inv2; o.w = f1 * inv2;
        *(float4*)&sO[(tA + 32) * 68 + h8] = o;
        upk2(ac2[2], f0, f1); o.x = f0 * inv2; o.y = f1 * inv2;
        upk2(ac2[3], f0, f1); o.z = f0 * inv2; o.w = f1 * inv2;
        *(float4*)&sO[(tA + 32) * 68 + h8 + 4] = o;
    }
    __syncthreads();

    // ================= MLP stages: tile 4t x 4j per thread =================
    const int jm = (tid & 15) * 4;
    const int tm = (tid >> 4) * 4;
    float* sM = sQ;                                // stride 68 (spills into dead sK)

    // ---------------- MLP stage 1: sM = gelu(sO @ W15^T + b15) ----------------
    {
        const float* sO = sH;
        unsigned long long a[4][2];
        #pragma unroll
        for (int r = 0; r < 4; r++) { a[r][0] = 0ull; a[r][1] = 0ull; }

        #pragma unroll 2
        for (int c4 = 0; c4 < 16; c4++) {
            const int cc = c4 << 2;
            float ha[4][4];
            #pragma unroll
            for (int r = 0; r < 4; r++) {
                float4 hv = *(const float4*)&sO[(tm + r) * 68 + cc];
                ha[r][0] = hv.x; ha[r][1] = hv.y; ha[r][2] = hv.z; ha[r][3] = hv.w;
            }
            #pragma unroll
            for (int i = 0; i < 4; i++) {
                const ulonglong2 w = *(const ulonglong2*)&sWc[(cc + i) * 64 + jm];
                #pragma unroll
                for (int r = 0; r < 4; r++) {
                    unsigned long long Hc = pk2(ha[r][i]);
                    a[r][0] = fma2(Hc, w.x, a[r][0]);
                    a[r][1] = fma2(Hc, w.y, a[r][1]);
                }
            }
        }
        const float4 bb = *(const float4*)&b15[jm];
        #pragma unroll
        for (int r = 0; r < 4; r++) {
            float f0, f1, f2, f3;
            upk2(a[r][0], f0, f1);
            upk2(a[r][1], f2, f3);
            float4 o;
            o.x = gelu_f(f0 + bb.x); o.y = gelu_f(f1 + bb.y);
            o.z = gelu_f(f2 + bb.z); o.w = gelu_f(f3 + bb.w);
            *(float4*)&sM[(tm + r) * 68 + jm] = o;
        }
    }
    __syncthreads();

    // ---------------- MLP stage 2: out = sM @ W16^T + b16 -> GMEM ----------------
    {
        const float* w16 = sH + 4352;              // W16t [64][64]
        unsigned long long a[4][2];
        #pragma unroll
        for (int r = 0; r < 4; r++) { a[r][0] = 0ull; a[r][1] = 0ull; }

        #pragma unroll 2
        for (int c4 = 0; c4 < 16; c4++) {
            const int cc = c4 << 2;
            float ha[4][4];
            #pragma unroll
            for (int r = 0; r < 4; r++) {
                float4 hv = *(const float4*)&sM[(tm + r) * 68 + cc];
                ha[r][0] = hv.x; ha[r][1] = hv.y; ha[r][2] = hv.z; ha[r][3] = hv.w;
            }
            #pragma unroll
            for (int i = 0; i < 4; i++) {
                const ulonglong2 w = *(const ulonglong2*)&w16[(cc + i) * 64 + jm];
                #pragma unroll
                for (int r = 0; r < 4; r++) {
                    unsigned long long Hc = pk2(ha[r][i]);
                    a[r][0] = fma2(Hc, w.x, a[r][0]);
                    a[r][1] = fma2(Hc, w.y, a[r][1]);
                }
            }
        }
        const float4 bb = *(const float4*)&b16[jm];
        #pragma unroll
        for (int r = 0; r < 4; r++) {
            float f0, f1, f2, f3;
            upk2(a[r][0], f0, f1);
            upk2(a[r][1], f2, f3);
            float4 o;
            o.x = f0 + bb.x; o.y = f1 + bb.y; o.z = f2 + bb.z; o.w = f3 + bb.w;
            *(float4*)&out[baseX + (tm + r) * ND_ + jm] = o;
        }
    }
}

extern "C" void kernel_launch(void* const* d_in, const int* in_sizes, int n_in,
                              void* d_out, int out_size)
{
    const float* X   = (const float*)d_in[0];
    const float* STE = (const float*)d_in[1];
    const float* W12 = (const float*)d_in[2];
    const float* b12 = (const float*)d_in[3];
    const float* W13 = (const float*)d_in[4];
    const float* b13 = (const float*)d_in[5];
    const float* W14 = (const float*)d_in[6];
    const float* b14 = (const float*)d_in[7];
    const float* W15 = (const float*)d_in[8];
    const float* b15 = (const float*)d_in[9];
    const float* W16 = (const float*)d_in[10];
    const float* b16 = (const float*)d_in[11];
    float* out = (float*)d_out;

    cudaFuncSetAttribute(tam_kernel,
                         cudaFuncAttributeMaxDynamicSharedMemorySize,
                         SMEM_FLOATS * (int)sizeof(float));

    transpose_weights<<<128, 256>>>(W12, W13, W14, W15, W16);

    dim3 grid(N_, B_);
    tam_kernel<<<grid, 256, SMEM_FLOATS * sizeof(float)>>>(
        X, STE, b12, b13, b14, b15, b16, out);
}

// round 17
// speedup vs baseline: 1.0013x; 1.0008x over previous
#include <cuda_runtime.h>
#include <math.h>

#define B_    16
#define T_    64
#define N_    256
#define D_    64
#define TWOD_ 128
#define ND_   16384   // N_*D_ : element stride between consecutive t rows

// Pre-transposed weights: W12t,W13t,W14t as [128][64]; W15t,W16t as [64][64]
__device__ __align__(16) float g_Wt[3 * TWOD_ * D_ + 2 * D_ * D_];   // 32768 floats

__global__ void transpose_weights(const float* __restrict__ W12,
                                  const float* __restrict__ W13,
                                  const float* __restrict__ W14,
                                  const float* __restrict__ W15,
                                  const float* __restrict__ W16)
{
    int idx = blockIdx.x * blockDim.x + threadIdx.x;
    if (idx < 8192) {
        int j = idx >> 7, c = idx & 127;
        g_Wt[c * 64 + j] = W12[idx];
    } else if (idx < 16384) {
        int k = idx - 8192; int j = k >> 7, c = k & 127;
        g_Wt[8192 + c * 64 + j] = W13[k];
    } else if (idx < 24576) {
        int k = idx - 16384; int j = k >> 7, c = k & 127;
        g_Wt[16384 + c * 64 + j] = W14[k];
    } else if (idx < 28672) {
        int k = idx - 24576; int j = k >> 6, c = k & 63;
        g_Wt[24576 + c * 64 + j] = W15[k];
    } else if (idx < 32768) {
        int k = idx - 28672; int j = k >> 6, c = k & 63;
        g_Wt[28672 + c * 64 + j] = W16[k];
    }
}

// ---------------- packed fp32x2 helpers (sm_103a FFMA2 path, PTX-only) ----------------
__device__ __forceinline__ unsigned long long pk2(float v) {
    unsigned long long r;
    asm("mov.b64 %0, {%1, %2};" : "=l"(r) : "f"(v), "f"(v));
    return r;
}
__device__ __forceinline__ void upk2(unsigned long long v, float& lo, float& hi) {
    asm("mov.b64 {%0, %1}, %2;" : "=f"(lo), "=f"(hi) : "l"(v));
}
__device__ __forceinline__ unsigned long long fma2(unsigned long long a,
                                                   unsigned long long b,
                                                   unsigned long long c) {
    unsigned long long d;
    asm("fma.rn.f32x2 %0, %1, %2, %3;" : "=l"(d) : "l"(a), "l"(b), "l"(c));
    return d;
}
__device__ __forceinline__ unsigned long long mul2(unsigned long long a,
                                                   unsigned long long b) {
    unsigned long long d;
    asm("mul.rn.f32x2 %0, %1, %2;" : "=l"(d) : "l"(a), "l"(b));
    return d;
}
__device__ __forceinline__ float psum2(unsigned long long v) {
    float lo, hi; upk2(v, lo, hi); return lo + hi;
}

__device__ __forceinline__ float gelu_f(float x) {
    // exact erf GELU (matches jax.nn.gelu(approximate=False))
    return 0.5f * x * (1.0f + erff(x * 0.7071067811865475f));
}

// SMEM layout (floats):
//   sH  @ 0     : 8704  (H 64x132=8448; reused: sO 64x68 @[0..4352), W16 buf @[4352..8448))
//   sWc @ 8704  : 6144  (QKV chunk: wQ/wK/wV 32x64 each; later W15t full in [0..4096))
//   sQ  @ 14848 : 4096  (later sM 64x68=4352, spilling into dead sK start)
//   sK  @ 18944 : 4096
//   sV  @ 23040 : 4096
// total 27136 floats = 108544 B -> 2 CTAs/SM
#define SMEM_FLOATS 27136

__global__ __launch_bounds__(256, 2)
void tam_kernel(const float* __restrict__ X,  const float* __restrict__ STE,
                const float* __restrict__ b12, const float* __restrict__ b13,
                const float* __restrict__ b14, const float* __restrict__ b15,
                const float* __restrict__ b16, float* __restrict__ out)
{
    extern __shared__ float sm[];
    float* sH  = sm;
    float* sWc = sm + 8704;
    float* sQ  = sm + 14848;
    float* sK  = sm + 18944;
    float* sV  = sm + 23040;

    const int n = blockIdx.x, b = blockIdx.y;
    const int tid = threadIdx.x;
    const int baseX = (b * T_ * N_ + n) * D_;

    // ---------------- load H = [X | STE] : 64 rows x 128, stride 132 ----------------
    for (int i = tid; i < T_ * TWOD_; i += 256) {
        int t = i >> 7, c = i & 127;
        int g = baseX + t * ND_ + (c & 63);
        sH[t * 132 + c] = (c < 64) ? X[g] : STE[g];
    }
    __syncthreads();

    // ================= fused QKV: tile 8t x 2j per thread =================
    // jq = j-pair base (one ulonglong of W per matrix per c), tq8 = 8-row block.
    // Per c-step: 8 H floats + 6 W floats feed 48 FMAs (24 FFMA2).
    const int jq  = (tid & 31) * 2;
    const int tq8 = (tid >> 5) * 8;

    unsigned long long aQ[8], aK[8], aV[8];
    #pragma unroll
    for (int r = 0; r < 8; r++) { aQ[r] = 0ull; aK[r] = 0ull; aV[r] = 0ull; }

    for (int ch = 0; ch < 4; ch++) {               // 4 chunks of 32 c-rows
        // cooperative load of 32x64 chunk of each of W12t/W13t/W14t (6144 floats)
        #pragma unroll
        for (int i = 0; i < 6; i++) {
            int k = i * 256 + tid;                 // float4 index 0..1535
            int m = k >> 9, off = (k & 511) << 2;
            *(float4*)&sWc[m * 2048 + off] =
                *(const float4*)&g_Wt[m * 8192 + ch * 2048 + off];
        }
        __syncthreads();

        #pragma unroll 2
        for (int c2 = 0; c2 < 16; c2++) {
            const int cc = (ch << 5) + (c2 << 1);
            float2 h[8];
            #pragma unroll
            for (int r = 0; r < 8; r++)
                h[r] = *(const float2*)&sH[(tq8 + r) * 132 + cc];

            #pragma unroll
            for (int i = 0; i < 2; i++) {
                const int c = (c2 << 1) + i;
                unsigned long long wq = *(const unsigned long long*)&sWc[c * 64 + jq];
                unsigned long long wk = *(const unsigned long long*)&sWc[2048 + c * 64 + jq];
                unsigned long long wv = *(const unsigned long long*)&sWc[4096 + c * 64 + jq];
                #pragma unroll
                for (int r = 0; r < 8; r++) {
                    unsigned long long Hc = pk2(i ? h[r].y : h[r].x);
                    aQ[r] = fma2(Hc, wq, aQ[r]);
                    aK[r] = fma2(Hc, wk, aK[r]);
                    aV[r] = fma2(Hc, wv, aV[r]);
                }
            }
        }
        __syncthreads();
    }

    // QKV epilogue: bias + exact gelu, store j-pair per row
    {
        const float2 bq = make_float2(b12[jq], b12[jq + 1]);
        const float2 bk = make_float2(b13[jq], b13[jq + 1]);
        const float2 bv = make_float2(b14[jq], b14[jq + 1]);
        #pragma unroll
        for (int r = 0; r < 8; r++) {
            float f0, f1;
            upk2(aQ[r], f0, f1);
            *(float2*)&sQ[(tq8 + r) * 64 + jq] =
                make_float2(gelu_f(f0 + bq.x), gelu_f(f1 + bq.y));
            upk2(aK[r], f0, f1);
            *(float2*)&sK[(tq8 + r) * 64 + jq] =
                make_float2(gelu_f(f0 + bk.x), gelu_f(f1 + bk.y));
            upk2(aV[r], f0, f1);
            *(float2*)&sV[(tq8 + r) * 64 + jq] =
                make_float2(gelu_f(f0 + bv.x), gelu_f(f1 + bv.y));
        }
    }
    __syncthreads();

    // ---------------- overlap: load W15 -> sWc[0..4096), W16 -> sH[4352..8448) ----------------
    #pragma unroll
    for (int i = 0; i < 4; i++) {
        int k = (i * 256 + tid) << 2;              // float offset 0..4092
        *(float4*)&sWc[k]        = *(const float4*)&g_Wt[24576 + k];
        *(float4*)&sH[4352 + k]  = *(const float4*)&g_Wt[28672 + k];
    }

    // ---------------- causal attention: two queries per thread, shared K/V loads ----------------
    // Logits are small enough (gelu-bounded q,k, d=8) that exp cannot overflow fp32;
    // softmax shift-invariance makes skipping the max pass exact up to rounding.
    {
        const int h8 = (tid & 7) * 8;
        const int tA = tid >> 3;                   // query A: tA, query B: tA + 32
        const float scale = 0.35355339059327376f;  // 1/sqrt(8)
        float* sO = sH;                            // output tile, stride 68, in [0..4352)

        const ulonglong2 q1a = *(const ulonglong2*)&sQ[tA * 64 + h8];
        const ulonglong2 q1b = *(const ulonglong2*)&sQ[tA * 64 + h8 + 4];
        const ulonglong2 q2a = *(const ulonglong2*)&sQ[(tA + 32) * 64 + h8];
        const ulonglong2 q2b = *(const ulonglong2*)&sQ[(tA + 32) * 64 + h8 + 4];

        unsigned long long ac1[4] = {0,0,0,0}, ac2[4] = {0,0,0,0};
        float s1 = 0.f, s2 = 0.f;

        // common range: s in [0, tA] — K/V loaded once, both queries updated
        #pragma unroll 2
        for (int s = 0; s <= tA; s++) {
            const ulonglong2 ka = *(const ulonglong2*)&sK[s * 64 + h8];
            const ulonglong2 kb = *(const ulonglong2*)&sK[s * 64 + h8 + 4];
            unsigned long long d1 = mul2(q1a.x, ka.x);
            d1 = fma2(q1a.y, ka.y, d1); d1 = fma2(q1b.x, kb.x, d1); d1 = fma2(q1b.y, kb.y, d1);
            unsigned long long d2 = mul2(q2a.x, ka.x);
            d2 = fma2(q2a.y, ka.y, d2); d2 = fma2(q2b.x, kb.x, d2); d2 = fma2(q2b.y, kb.y, d2);
            float e1 = __expf(psum2(d1) * scale);
            float e2 = __expf(psum2(d2) * scale);
            s1 += e1; s2 += e2;
            const ulonglong2 va = *(const ulonglong2*)&sV[s * 64 + h8];
            const ulonglong2 vb = *(const ulonglong2*)&sV[s * 64 + h8 + 4];
            unsigned long long E1 = pk2(e1), E2 = pk2(e2);
            ac1[0] = fma2(E1, va.x, ac1[0]); ac1[1] = fma2(E1, va.y, ac1[1]);
            ac1[2] = fma2(E1, vb.x, ac1[2]); ac1[3] = fma2(E1, vb.y, ac1[3]);
            ac2[0] = fma2(E2, va.x, ac2[0]); ac2[1] = fma2(E2, va.y, ac2[1]);
            ac2[2] = fma2(E2, vb.x, ac2[2]); ac2[3] = fma2(E2, vb.y, ac2[3]);
        }
        // tail range: s in (tA, tA+32] — query B only; fixed 32 trips, no divergence
        #pragma unroll 4
        for (int k2 = 1; k2 <= 32; k2++) {
            const int s = tA + k2;
            const ulonglong2 ka = *(const ulonglong2*)&sK[s * 64 + h8];
            const ulonglong2 kb = *(const ulonglong2*)&sK[s * 64 + h8 + 4];
            unsigned long long d2 = mul2(q2a.x, ka.x);
            d2 = fma2(q2a.y, ka.y, d2); d2 = fma2(q2b.x, kb.x, d2); d2 = fma2(q2b.y, kb.y, d2);
            float e2 = __expf(psum2(d2) * scale);
            s2 += e2;
            const ulonglong2 va = *(const ulonglong2*)&sV[s * 64 + h8];
            const ulonglong2 vb = *(const ulonglong2*)&sV[s * 64 + h8 + 4];
            unsigned long long E2 = pk2(e2);
            ac2[0] = fma2(E2, va.x, ac2[0]); ac2[1] = fma2(E2, va.y, ac2[1]);
            ac2[2] = fma2(E2, vb.x, ac2[2]); ac2[3] = fma2(E2, vb.y, ac2[3]);
        }

        float inv1 = 1.0f / s1, inv2 = 1.0f / s2;
        float f0, f1;
        float4 o;
        upk2(ac1[0], f0, f1); o.x = f0 * inv1; o.y = f1 * inv1;
        upk2(ac1[1], f0, f1); o.z = f0 * inv1; o.w = f1 * inv1;
        *(float4*)&sO[tA * 68 + h8] = o;
        upk2(ac1[2], f0, f1); o.x = f0 * inv1; o.y = f1 * inv1;
        upk2(ac1[3], f0, f1); o.z = f0 * inv1; o.w = f1 * inv1;
        *(float4*)&sO[tA * 68 + h8 + 4] = o;
        upk2(ac2[0], f0, f1); o.x = f0 * inv2; o.y = f1 * inv2;
        upk2(ac2[1], f0, f1); o.z = f0 * inv2; o.w = f1 * inv2;
        *(float4*)&sO[(tA + 32) * 68 + h8] = o;
        upk2(ac2[2], f0, f1); o.x = f0 * inv2; o.y = f1 * inv2;
        upk2(ac2[3], f0, f1); o.z = f0 * inv2; o.w = f1 * inv2;
        *(float4*)&sO[(tA + 32) * 68 + h8 + 4] = o;
    }
    __syncthreads();

    // ================= MLP stages: tile 4t x 4j per thread =================
    const int jm = (tid & 15) * 4;
    const int tm = (tid >> 4) * 4;
    float* sM = sQ;                                // stride 68 (spills into dead sK)

    // ---------------- MLP stage 1: sM = gelu(sO @ W15^T + b15) ----------------
    {
        const float* sO = sH;
        unsigned long long a[4][2];
        #pragma unroll
        for (int r = 0; r < 4; r++) { a[r][0] = 0ull; a[r][1] = 0ull; }

        #pragma unroll 2
        for (int c4 = 0; c4 < 16; c4++) {
            const int cc = c4 << 2;
            float ha[4][4];
            #pragma unroll
            for (int r = 0; r < 4; r++) {
                float4 hv = *(const float4*)&sO[(tm + r) * 68 + cc];
                ha[r][0] = hv.x; ha[r][1] = hv.y; ha[r][2] = hv.z; ha[r][3] = hv.w;
            }
            #pragma unroll
            for (int i = 0; i < 4; i++) {
                const ulonglong2 w = *(const ulonglong2*)&sWc[(cc + i) * 64 + jm];
                #pragma unroll
                for (int r = 0; r < 4; r++) {
                    unsigned long long Hc = pk2(ha[r][i]);
                    a[r][0] = fma2(Hc, w.x, a[r][0]);
                    a[r][1] = fma2(Hc, w.y, a[r][1]);
                }
            }
        }
        const float4 bb = *(const float4*)&b15[jm];
        #pragma unroll
        for (int r = 0; r < 4; r++) {
            float f0, f1, f2, f3;
            upk2(a[r][0], f0, f1);
            upk2(a[r][1], f2, f3);
            float4 o;
            o.x = gelu_f(f0 + bb.x); o.y = gelu_f(f1 + bb.y);
            o.z = gelu_f(f2 + bb.z); o.w = gelu_f(f3 + bb.w);
            *(float4*)&sM[(tm + r) * 68 + jm] = o;
        }
    }
    __syncthreads();

    // ---------------- MLP stage 2: out = sM @ W16^T + b16 -> GMEM ----------------
    {
        const float* w16 = sH + 4352;              // W16t [64][64]
        unsigned long long a[4][2];
        #pragma unroll
        for (int r = 0; r < 4; r++) { a[r][0] = 0ull; a[r][1] = 0ull; }

        #pragma unroll 2
        for (int c4 = 0; c4 < 16; c4++) {
            const int cc = c4 << 2;
            float ha[4][4];
            #pragma unroll
            for (int r = 0; r < 4; r++) {
                float4 hv = *(const float4*)&sM[(tm + r) * 68 + cc];
                ha[r][0] = hv.x; ha[r][1] = hv.y; ha[r][2] = hv.z; ha[r][3] = hv.w;
            }
            #pragma unroll
            for (int i = 0; i < 4; i++) {
                const ulonglong2 w = *(const ulonglong2*)&w16[(cc + i) * 64 + jm];
                #pragma unroll
                for (int r = 0; r < 4; r++) {
                    unsigned long long Hc = pk2(ha[r][i]);
                    a[r][0] = fma2(Hc, w.x, a[r][0]);
                    a[r][1] = fma2(Hc, w.y, a[r][1]);
                }
            }
        }
        const float4 bb = *(const float4*)&b16[jm];
        #pragma unroll
        for (int r = 0; r < 4; r++) {
            float f0, f1, f2, f3;
            upk2(a[r][0], f0, f1);
            upk2(a[r][1], f2, f3);
            float4 o;
            o.x = f0 + bb.x; o.y = f1 + bb.y; o.z = f2 + bb.z; o.w = f3 + bb.w;
            *(float4*)&out[baseX + (tm + r) * ND_ + jm] = o;
        }
    }
}

extern "C" void kernel_launch(void* const* d_in, const int* in_sizes, int n_in,
                              void* d_out, int out_size)
{
    const float* X   = (const float*)d_in[0];
    const float* STE = (const float*)d_in[1];
    const float* W12 = (const float*)d_in[2];
    const float* b12 = (const float*)d_in[3];
    const float* W13 = (const float*)d_in[4];
    const float* b13 = (const float*)d_in[5];
    const float* W14 = (const float*)d_in[6];
    const float* b14 = (const float*)d_in[7];
    const float* W15 = (const float*)d_in[8];
    const float* b15 = (const float*)d_in[9];
    const float* W16 = (const float*)d_in[10];
    const float* b16 = (const float*)d_in[11];
    float* out = (float*)d_out;

    cudaFuncSetAttribute(tam_kernel,
                         cudaFuncAttributeMaxDynamicSharedMemorySize,
                         SMEM_FLOATS * (int)sizeof(float));

    transpose_weights<<<128, 256>>>(W12, W13, W14, W15, W16);

    dim3 grid(N_, B_);
    tam_kernel<<<grid, 256, SMEM_FLOATS * sizeof(float)>>>(
        X, STE, b12, b13, b14, b15, b16, out);
}